// round 15
// baseline (speedup 1.0000x reference)
#include <cuda_runtime.h>
#include <cuda_fp16.h>
#include <cstdint>

#define S_LEN 4096
#define D_MODEL 768
#define NHEAD 12
#define WHEAD 64
#define N_QKV 2304
#define NSPLIT 4
#define NT_KV (S_LEN / 32)
#define NT_PER (NT_KV / NSPLIT)

// ---------------- scratch ----------------
__device__ __half g_xh[S_LEN * D_MODEL];        // X in fp16 [s][k]
__device__ __half g_wh[N_QKV * D_MODEL];        // W^T in fp16 [n][k]
__device__ __half g_q[NHEAD * S_LEN * WHEAD];   // [h][s][w] fp16
__device__ __half g_k[NHEAD * S_LEN * WHEAD];   // [h][s][w] fp16
__device__ __half g_vt[NHEAD * WHEAD * S_LEN];  // [h][w][s] fp16 (transposed)
__device__ float g_os[NSPLIT * NHEAD * S_LEN * WHEAD];
__device__ float g_ls[NSPLIT * NHEAD * S_LEN];

// ---------------- helpers ----------------
__device__ __forceinline__ float ex2(float x) {
    float y;
    asm("ex2.approx.f32 %0, %1;" : "=f"(y) : "f"(x));
    return y;
}
// pack (lo,hi) floats -> f16x2 (lo in bits[15:0])
__device__ __forceinline__ uint32_t pack2(float lo, float hi) {
    uint32_t r;
    asm("cvt.rn.f16x2.f32 %0, %1, %2;" : "=r"(r) : "f"(hi), "f"(lo));
    return r;
}

__device__ __forceinline__ void mma_f16(
    float& d0, float& d1, float& d2, float& d3,
    uint32_t a0, uint32_t a1, uint32_t a2, uint32_t a3,
    uint32_t b0, uint32_t b1)
{
    asm volatile(
        "mma.sync.aligned.m16n8k16.row.col.f32.f16.f16.f32 "
        "{%0,%1,%2,%3},{%4,%5,%6,%7},{%8,%9},{%0,%1,%2,%3};"
        : "+f"(d0), "+f"(d1), "+f"(d2), "+f"(d3)
        : "r"(a0), "r"(a1), "r"(a2), "r"(a3), "r"(b0), "r"(b1));
}

__device__ __forceinline__ void cpa16(void* s, const void* g) {
    uint32_t sa = (uint32_t)__cvta_generic_to_shared(s);
    asm volatile("cp.async.cg.shared.global [%0], [%1], 16;" :: "r"(sa), "l"(g));
}
#define CPA_COMMIT() asm volatile("cp.async.commit_group;" ::: "memory")
#define CPA_WAIT0()  asm volatile("cp.async.wait_group 0;" ::: "memory")
#define CPA_WAIT1()  asm volatile("cp.async.wait_group 1;" ::: "memory")

// =============== Kernel 0a: convert X -> fp16 ===============
__global__ __launch_bounds__(256) void conv_x(const float* __restrict__ X)
{
    int idx = blockIdx.x * 256 + threadIdx.x;          // per float4
    float4 v = *(const float4*)&X[idx * 4];
    uint2 u = make_uint2(pack2(v.x, v.y), pack2(v.z, v.w));
    *(uint2*)&g_xh[idx * 4] = u;
}

// =============== Kernel 0b: transpose+convert W[k][n] -> Wh[n][k] fp16 ===============
__global__ __launch_bounds__(256) void conv_w(const float* __restrict__ W)
{
    __shared__ float tile[32][33];
    const int tx = threadIdx.x & 31;
    const int ty = threadIdx.x >> 5;      // 0..7
    const int n0 = blockIdx.x * 32;
    const int k0 = blockIdx.y * 32;
#pragma unroll
    for (int r = 0; r < 32; r += 8)
        tile[ty + r][tx] = W[(size_t)(k0 + ty + r) * N_QKV + n0 + tx];
    __syncthreads();
#pragma unroll
    for (int r = 0; r < 32; r += 8)
        g_wh[(size_t)(n0 + ty + r) * D_MODEL + k0 + tx] =
            __float2half_rn(tile[tx][ty + r]);
}

// =============== Kernel 1: QKV GEMM (fp16 m16n8k16, cp.async double-buffered) ===============
// 128x64 block tile, BK=64, 256 threads = 8 warps (4m x 2n), warp 32x32.
#define GP 72   // half pitch; word-stride 36 == 4 (mod 32) -> conflict-free
#define GA_SZ (128 * GP)   // 9216 halves
#define GB_SZ (64 * GP)    // 4608 halves
#define GEMM_SMEM_BYTES ((GA_SZ + GB_SZ) * 2 * 2)   // 55296 B

__global__ __launch_bounds__(256) void qkv_gemm_f16(
    const float* __restrict__ bq)
{
    extern __shared__ __half gsm[];
    __half* Ah[2] = { gsm, gsm + GA_SZ + GB_SZ };
    __half* Bh[2] = { gsm + GA_SZ, gsm + GA_SZ + GB_SZ + GA_SZ };

    const int tid = threadIdx.x;
    const int wid = tid >> 5;
    const int lane = tid & 31;
    const int g = lane >> 2;
    const int c = lane & 3;
    const int warp_m = wid >> 1;
    const int warp_n = wid & 1;
    const int m0 = blockIdx.y * 128;
    const int n0 = blockIdx.x * 64;

    float acc[2][4][4];
#pragma unroll
    for (int mt = 0; mt < 2; ++mt)
#pragma unroll
        for (int nt = 0; nt < 4; ++nt)
#pragma unroll
            for (int i = 0; i < 4; ++i) acc[mt][nt][i] = 0.0f;

    const int rw = tid >> 3, c8 = tid & 7;   // row, 16B-chunk

    auto issue = [&](int k0, int buf) {
#pragma unroll
        for (int r = 0; r < 4; ++r) {        // A: 128 rows x 8 chunks
            int row = rw + r * 32;
            cpa16(&Ah[buf][row * GP + c8 * 8],
                  &g_xh[(size_t)(m0 + row) * D_MODEL + k0 + c8 * 8]);
        }
#pragma unroll
        for (int r = 0; r < 2; ++r) {        // B: 64 rows x 8 chunks
            int row = rw + r * 32;
            cpa16(&Bh[buf][row * GP + c8 * 8],
                  &g_wh[(size_t)(n0 + row) * D_MODEL + k0 + c8 * 8]);
        }
        CPA_COMMIT();
    };

    issue(0, 0);
    for (int i = 0; i < 12; ++i) {
        CPA_WAIT0();
        __syncthreads();
        if (i + 1 < 12) issue((i + 1) * 64, (i + 1) & 1);
        const __half* A = Ah[i & 1];
        const __half* B = Bh[i & 1];
#pragma unroll
        for (int kk = 0; kk < 4; ++kk) {
            uint32_t af[2][4];
#pragma unroll
            for (int mt = 0; mt < 2; ++mt) {
                int mr = warp_m * 32 + mt * 16 + g;
                af[mt][0] = *(const uint32_t*)&A[mr * GP + kk * 16 + 2 * c];
                af[mt][1] = *(const uint32_t*)&A[(mr + 8) * GP + kk * 16 + 2 * c];
                af[mt][2] = *(const uint32_t*)&A[mr * GP + kk * 16 + 8 + 2 * c];
                af[mt][3] = *(const uint32_t*)&A[(mr + 8) * GP + kk * 16 + 8 + 2 * c];
            }
#pragma unroll
            for (int nt = 0; nt < 4; ++nt) {
                int col = warp_n * 32 + nt * 8 + g;
                uint32_t b0 = *(const uint32_t*)&B[col * GP + kk * 16 + 2 * c];
                uint32_t b1 = *(const uint32_t*)&B[col * GP + kk * 16 + 8 + 2 * c];
#pragma unroll
                for (int mt = 0; mt < 2; ++mt)
                    mma_f16(acc[mt][nt][0], acc[mt][nt][1], acc[mt][nt][2], acc[mt][nt][3],
                            af[mt][0], af[mt][1], af[mt][2], af[mt][3], b0, b1);
            }
        }
        __syncthreads();
    }

    const int sel = n0 / D_MODEL;
    const int head = (n0 % D_MODEL) / WHEAD;

#pragma unroll
    for (int mt = 0; mt < 2; ++mt) {
#pragma unroll
        for (int nt = 0; nt < 4; ++nt) {
            int w = warp_n * 32 + nt * 8 + 2 * c;
            float b0 = bq[n0 + w], b1 = bq[n0 + w + 1];
            int m_lo = m0 + warp_m * 32 + mt * 16 + g;
            float v00 = acc[mt][nt][0] + b0;
            float v01 = acc[mt][nt][1] + b1;
            float v10 = acc[mt][nt][2] + b0;
            float v11 = acc[mt][nt][3] + b1;
            if (sel == 2) {   // V transposed: [h][w][s]
                __half* vt = g_vt + (size_t)head * WHEAD * S_LEN;
                vt[(size_t)w * S_LEN + m_lo] = __float2half_rn(v00);
                vt[(size_t)(w + 1) * S_LEN + m_lo] = __float2half_rn(v01);
                vt[(size_t)w * S_LEN + m_lo + 8] = __float2half_rn(v10);
                vt[(size_t)(w + 1) * S_LEN + m_lo + 8] = __float2half_rn(v11);
            } else {          // Q/K natural: [h][s][w]
                __half* dst = (sel == 0) ? g_q : g_k;
                *(__half2*)&dst[((size_t)head * S_LEN + m_lo) * WHEAD + w] =
                    __floats2half2_rn(v00, v01);
                *(__half2*)&dst[((size_t)head * S_LEN + m_lo + 8) * WHEAD + w] =
                    __floats2half2_rn(v10, v11);
            }
        }
    }
}

// =============== Kernel 2: flash attention (fp16 MMA, BC=32, split-KV x4) ===============
#define QP  72
#define KPH 72
#define VPH 40
#define SM_Q   0
#define SM_K   (128 * QP)
#define SM_V   (SM_K + 32 * KPH)
#define SM_END (SM_V + 64 * VPH)
#define SM_AM_F (SM_END / 2)
#define ATTN_SMEM_BYTES (SM_END * 2 + 2 * 32 * 4)   // 28416 B

#define LOG2E 1.4426950408889634f
#define SCL   (0.125f * LOG2E)
#define AMC   (10000.0f * LOG2E)

__global__ __launch_bounds__(128, 4) void attn_tc(
    const float* __restrict__ mask)
{
    extern __shared__ __half smh[];
    float* smf = (float*)smh;

    const int tid = threadIdx.x;
    const int wid = tid >> 5;
    const int lane = tid & 31;
    const int g = lane >> 2;
    const int c = lane & 3;
    const int r0 = blockIdx.x * 128;
    const int head = blockIdx.y;
    const int split = blockIdx.z;
    const int tb = split * NT_PER;

    const __half* qh = g_q + (size_t)head * S_LEN * WHEAD;
    const __half* kh = g_k + (size_t)head * S_LEN * WHEAD;
    const __half* vt = g_vt + (size_t)head * WHEAD * S_LEN;

    const int r8 = tid >> 3, c8 = tid & 7;
    const int r4 = tid >> 2, c4 = tid & 3;

    auto issueK = [&](int t0) {
#pragma unroll
        for (int r = 0; r < 2; ++r) {
            int row = r8 + r * 16;
            cpa16(&smh[SM_K + row * KPH + c8 * 8],
                  &kh[(size_t)(t0 + row) * WHEAD + c8 * 8]);
        }
        if (tid < 8) cpa16(&smf[SM_AM_F + ((t0 >> 5) & 1) * 32 + tid * 4], &mask[t0 + tid * 4]);
    };
    auto issueV = [&](int t0) {
#pragma unroll
        for (int r = 0; r < 2; ++r) {
            int w = r4 + r * 32;
            cpa16(&smh[SM_V + w * VPH + c4 * 8],
                  &vt[(size_t)w * S_LEN + t0 + c4 * 8]);
        }
    };

    // ---- prologue ----
#pragma unroll
    for (int r = 0; r < 8; ++r) {
        int row = r8 + r * 16;
        cpa16(&smh[SM_Q + row * QP + c8 * 8],
              &qh[(size_t)(r0 + row) * WHEAD + c8 * 8]);
    }
    issueK(tb * 32);
    issueV(tb * 32);
    CPA_COMMIT();

    float oacc[2][8][4];
#pragma unroll
    for (int mt = 0; mt < 2; ++mt)
#pragma unroll
        for (int nt = 0; nt < 8; ++nt)
#pragma unroll
            for (int i = 0; i < 4; ++i) oacc[mt][nt][i] = 0.0f;
    float lrow[2][2];
    lrow[0][0] = lrow[0][1] = lrow[1][0] = lrow[1][1] = 0.0f;

    CPA_WAIT0();
    __syncthreads();

    for (int tt = 0; tt < NT_PER; ++tt) {
        const int t = tb + tt;

        // ---- S = Q K^T : fp16 m16n8k16, 4 k-steps ----
        float sacc[2][4][4];
#pragma unroll
        for (int mt = 0; mt < 2; ++mt)
#pragma unroll
            for (int nt = 0; nt < 4; ++nt)
#pragma unroll
                for (int i = 0; i < 4; ++i) sacc[mt][nt][i] = 0.0f;

#pragma unroll
        for (int kk = 0; kk < 4; ++kk) {
            uint32_t af[2][4];
#pragma unroll
            for (int mt = 0; mt < 2; ++mt) {
                int mr = wid * 32 + mt * 16 + g;
                af[mt][0] = *(const uint32_t*)&smh[SM_Q + mr * QP + kk * 16 + 2 * c];
                af[mt][1] = *(const uint32_t*)&smh[SM_Q + (mr + 8) * QP + kk * 16 + 2 * c];
                af[mt][2] = *(const uint32_t*)&smh[SM_Q + mr * QP + kk * 16 + 8 + 2 * c];
                af[mt][3] = *(const uint32_t*)&smh[SM_Q + (mr + 8) * QP + kk * 16 + 8 + 2 * c];
            }
#pragma unroll
            for (int nt = 0; nt < 4; ++nt) {
                int kr = nt * 8 + g;
                uint32_t b0 = *(const uint32_t*)&smh[SM_K + kr * KPH + kk * 16 + 2 * c];
                uint32_t b1 = *(const uint32_t*)&smh[SM_K + kr * KPH + kk * 16 + 8 + 2 * c];
#pragma unroll
                for (int mt = 0; mt < 2; ++mt)
                    mma_f16(sacc[mt][nt][0], sacc[mt][nt][1], sacc[mt][nt][2], sacc[mt][nt][3],
                            af[mt][0], af[mt][1], af[mt][2], af[mt][3], b0, b1);
            }
        }

        __syncthreads();                   // K readers done
        if (tt + 1 < NT_PER) issueK((t + 1) * 32);
        CPA_COMMIT();                      // group = K(t+1)+mask(t+1)

        // ---- static-max softmax ----
        {
            float amv[4][2];
#pragma unroll
            for (int nt = 0; nt < 4; ++nt) {
                float m0v = smf[SM_AM_F + (t & 1) * 32 + nt * 8 + 2 * c];
                float m1v = smf[SM_AM_F + (t & 1) * 32 + nt * 8 + 2 * c + 1];
                amv[nt][0] = fmaf(m0v, AMC, -AMC);
                amv[nt][1] = fmaf(m1v, AMC, -AMC);
            }
#pragma unroll
            for (int mt = 0; mt < 2; ++mt) {
#pragma unroll
                for (int nt = 0; nt < 4; ++nt) {
                    float p0 = ex2(fmaf(sacc[mt][nt][0], SCL, amv[nt][0]));
                    float p1 = ex2(fmaf(sacc[mt][nt][1], SCL, amv[nt][1]));
                    float p2 = ex2(fmaf(sacc[mt][nt][2], SCL, amv[nt][0]));
                    float p3 = ex2(fmaf(sacc[mt][nt][3], SCL, amv[nt][1]));
                    lrow[mt][0] += p0 + p1;
                    lrow[mt][1] += p2 + p3;
                    sacc[mt][nt][0] = p0;
                    sacc[mt][nt][1] = p1;
                    sacc[mt][nt][2] = p2;
                    sacc[mt][nt][3] = p3;
                }
            }
        }

        CPA_WAIT1();                       // V(t)'s group (older) retired
        __syncthreads();

        // ---- O += P V : fp16 m16n8k16, 2 k-steps; A-frags = packed C-frags ----
#pragma unroll
        for (int q = 0; q < 2; ++q) {
            uint32_t af[2][4];
#pragma unroll
            for (int mt = 0; mt < 2; ++mt) {
                af[mt][0] = pack2(sacc[mt][2 * q][0], sacc[mt][2 * q][1]);
                af[mt][1] = pack2(sacc[mt][2 * q][2], sacc[mt][2 * q][3]);
                af[mt][2] = pack2(sacc[mt][2 * q + 1][0], sacc[mt][2 * q + 1][1]);
                af[mt][3] = pack2(sacc[mt][2 * q + 1][2], sacc[mt][2 * q + 1][3]);
            }
#pragma unroll
            for (int nt = 0; nt < 8; ++nt) {
                int vr = nt * 8 + g;
                uint32_t b0 = *(const uint32_t*)&smh[SM_V + vr * VPH + q * 16 + 2 * c];
                uint32_t b1 = *(const uint32_t*)&smh[SM_V + vr * VPH + q * 16 + 8 + 2 * c];
#pragma unroll
                for (int mt = 0; mt < 2; ++mt)
                    mma_f16(oacc[mt][nt][0], oacc[mt][nt][1], oacc[mt][nt][2], oacc[mt][nt][3],
                            af[mt][0], af[mt][1], af[mt][2], af[mt][3], b0, b1);
            }
        }

        __syncthreads();                   // V readers done
        if (tt + 1 < NT_PER) issueV((t + 1) * 32);
        CPA_COMMIT();                      // group = V(t+1)
        CPA_WAIT1();                       // K(t+1) retired
        __syncthreads();
    }

    // ---- epilogue ----
    float* op = g_os + ((size_t)(split * NHEAD + head) * S_LEN) * WHEAD;
    float* lp = g_ls + (size_t)(split * NHEAD + head) * S_LEN;
#pragma unroll
    for (int mt = 0; mt < 2; ++mt) {
#pragma unroll
        for (int off = 1; off <= 2; off <<= 1) {
            lrow[mt][0] += __shfl_xor_sync(0xffffffffu, lrow[mt][0], off);
            lrow[mt][1] += __shfl_xor_sync(0xffffffffu, lrow[mt][1], off);
        }
        int row_lo = r0 + wid * 32 + mt * 16 + g;
        if (c == 0) {
            lp[row_lo] = lrow[mt][0];
            lp[row_lo + 8] = lrow[mt][1];
        }
#pragma unroll
        for (int nt = 0; nt < 8; ++nt) {
            int col = nt * 8 + 2 * c;
            *(float2*)&op[(size_t)row_lo * WHEAD + col] =
                make_float2(oacc[mt][nt][0], oacc[mt][nt][1]);
            *(float2*)&op[(size_t)(row_lo + 8) * WHEAD + col] =
                make_float2(oacc[mt][nt][2], oacc[mt][nt][3]);
        }
    }
}

// =============== Kernel 3: combine splits ===============
__global__ __launch_bounds__(256) void combine_k(float* __restrict__ out)
{
    int idx = blockIdx.x * 256 + threadIdx.x;
    int w4 = idx & 15;
    int hs = idx >> 4;
    int h = hs % NHEAD;
    int s = hs / NHEAD;

    float4 o = make_float4(0.f, 0.f, 0.f, 0.f);
    float l = 0.f;
#pragma unroll
    for (int p = 0; p < NSPLIT; ++p) {
        const float* op = g_os + (((size_t)(p * NHEAD + h) * S_LEN + s) * WHEAD);
        float4 v = *(const float4*)&op[w4 * 4];
        o.x += v.x; o.y += v.y; o.z += v.z; o.w += v.w;
        l += g_ls[(size_t)(p * NHEAD + h) * S_LEN + s];
    }
    float inv = 1.0f / l;
    o.x *= inv; o.y *= inv; o.z *= inv; o.w *= inv;
    *(float4*)&out[(size_t)s * D_MODEL + h * WHEAD + w4 * 4] = o;
}

// ---------------- launch ----------------
extern "C" void kernel_launch(void* const* d_in, const int* in_sizes, int n_in,
                              void* d_out, int out_size)
{
    const float* x    = (const float*)d_in[0];
    const float* mask = (const float*)d_in[1];
    const float* Wq   = (const float*)d_in[2];
    const float* bq   = (const float*)d_in[3];
    float* out = (float*)d_out;

    conv_x<<<(S_LEN * D_MODEL / 4) / 256, 256>>>(x);          // 3072 blocks
    conv_w<<<dim3(N_QKV / 32, D_MODEL / 32), 256>>>(Wq);      // (72, 24)

    cudaFuncSetAttribute(qkv_gemm_f16,
                         cudaFuncAttributeMaxDynamicSharedMemorySize,
                         GEMM_SMEM_BYTES);
    dim3 gGemm(N_QKV / 64, S_LEN / 128);                      // (36, 32)
    qkv_gemm_f16<<<gGemm, 256, GEMM_SMEM_BYTES>>>(bq);

    cudaFuncSetAttribute(attn_tc,
                         cudaFuncAttributeMaxDynamicSharedMemorySize,
                         ATTN_SMEM_BYTES);
    dim3 gAttn(S_LEN / 128, NHEAD, NSPLIT);                   // (32, 12, 4)
    attn_tc<<<gAttn, 128, ATTN_SMEM_BYTES>>>(mask);

    combine_k<<<(S_LEN * NHEAD * 16) / 256, 256>>>(out);
}

// round 16
// speedup vs baseline: 1.4817x; 1.4817x over previous
#include <cuda_runtime.h>
#include <cuda_fp16.h>
#include <cstdint>

#define S_LEN 4096
#define D_MODEL 768
#define NHEAD 12
#define WHEAD 64
#define N_QKV 2304
#define NSPLIT 4
#define NT_KV (S_LEN / 32)
#define NT_PER (NT_KV / NSPLIT)

// ---------------- scratch ----------------
__device__ __half g_q[NHEAD * S_LEN * WHEAD];   // [h][s][w] fp16
__device__ __half g_k[NHEAD * S_LEN * WHEAD];   // [h][s][w] fp16
__device__ __half g_vt[NHEAD * WHEAD * S_LEN];  // [h][w][s] fp16 (transposed)
__device__ float g_os[NSPLIT * NHEAD * S_LEN * WHEAD];
__device__ float g_ls[NSPLIT * NHEAD * S_LEN];

// ---------------- helpers ----------------
__device__ __forceinline__ uint32_t f2tf32(float x) {
    uint32_t u;
    asm("cvt.rna.tf32.f32 %0, %1;" : "=r"(u) : "f"(x));
    return u;
}
__device__ __forceinline__ float ex2(float x) {
    float y;
    asm("ex2.approx.f32 %0, %1;" : "=f"(y) : "f"(x));
    return y;
}
// pack (lo,hi) floats -> f16x2 (lo in bits[15:0])
__device__ __forceinline__ uint32_t pack2(float lo, float hi) {
    uint32_t r;
    asm("cvt.rn.f16x2.f32 %0, %1, %2;" : "=r"(r) : "f"(hi), "f"(lo));
    return r;
}

__device__ __forceinline__ void mma_tf32(
    float& d0, float& d1, float& d2, float& d3,
    uint32_t a0, uint32_t a1, uint32_t a2, uint32_t a3,
    uint32_t b0, uint32_t b1)
{
    asm volatile(
        "mma.sync.aligned.m16n8k8.row.col.f32.tf32.tf32.f32 "
        "{%0,%1,%2,%3},{%4,%5,%6,%7},{%8,%9},{%0,%1,%2,%3};"
        : "+f"(d0), "+f"(d1), "+f"(d2), "+f"(d3)
        : "r"(a0), "r"(a1), "r"(a2), "r"(a3), "r"(b0), "r"(b1));
}

__device__ __forceinline__ void mma_f16(
    float& d0, float& d1, float& d2, float& d3,
    uint32_t a0, uint32_t a1, uint32_t a2, uint32_t a3,
    uint32_t b0, uint32_t b1)
{
    asm volatile(
        "mma.sync.aligned.m16n8k16.row.col.f32.f16.f16.f32 "
        "{%0,%1,%2,%3},{%4,%5,%6,%7},{%8,%9},{%0,%1,%2,%3};"
        : "+f"(d0), "+f"(d1), "+f"(d2), "+f"(d3)
        : "r"(a0), "r"(a1), "r"(a2), "r"(a3), "r"(b0), "r"(b1));
}

__device__ __forceinline__ void cpa16(void* s, const void* g) {
    uint32_t sa = (uint32_t)__cvta_generic_to_shared(s);
    asm volatile("cp.async.cg.shared.global [%0], [%1], 16;" :: "r"(sa), "l"(g));
}
#define CPA_COMMIT() asm volatile("cp.async.commit_group;" ::: "memory")
#define CPA_WAIT0()  asm volatile("cp.async.wait_group 0;" ::: "memory")
#define CPA_WAIT1()  asm volatile("cp.async.wait_group 1;" ::: "memory")

// =============== Kernel 1: QKV GEMM (tf32 compute, fp16 outputs) ===============
#define GAP 36
#define GBP 72

__global__ __launch_bounds__(256) void qkv_gemm_tc(
    const float* __restrict__ X, const float* __restrict__ Wq,
    const float* __restrict__ bq)
{
    __shared__ float As[2][128 * GAP];
    __shared__ float Bs[2][32 * GBP];

    const int tid = threadIdx.x;
    const int wid = tid >> 5;
    const int lane = tid & 31;
    const int g = lane >> 2;
    const int c = lane & 3;
    const int warp_m = wid >> 1;
    const int warp_n = wid & 1;
    const int m0 = blockIdx.y * 128;
    const int n0 = blockIdx.x * 64;

    float acc[2][4][4];
#pragma unroll
    for (int mt = 0; mt < 2; ++mt)
#pragma unroll
        for (int nt = 0; nt < 4; ++nt)
#pragma unroll
            for (int i = 0; i < 4; ++i) acc[mt][nt][i] = 0.0f;

    const int rowA = tid >> 3, c4A = tid & 7;
    const int rowB = tid >> 4, c4B = tid & 15;

    auto issue = [&](int k0, int buf) {
#pragma unroll
        for (int r = 0; r < 4; ++r) {
            int row = rowA + r * 32;
            cpa16(&As[buf][row * GAP + c4A * 4],
                  &X[(size_t)(m0 + row) * D_MODEL + k0 + c4A * 4]);
        }
#pragma unroll
        for (int r = 0; r < 2; ++r) {
            int row = rowB + r * 16;
            cpa16(&Bs[buf][row * GBP + c4B * 4],
                  &Wq[(size_t)(k0 + row) * N_QKV + n0 + c4B * 4]);
        }
        CPA_COMMIT();
    };

    issue(0, 0);
    for (int i = 0; i < 24; ++i) {
        CPA_WAIT0();
        __syncthreads();
        if (i + 1 < 24) issue((i + 1) * 32, (i + 1) & 1);
        const float* A = As[i & 1];
        const float* B = Bs[i & 1];
#pragma unroll
        for (int kk = 0; kk < 4; ++kk) {
            uint32_t af[2][4];
#pragma unroll
            for (int mt = 0; mt < 2; ++mt) {
                int mr = warp_m * 32 + mt * 16 + g;
                af[mt][0] = f2tf32(A[mr * GAP + kk * 8 + c]);
                af[mt][1] = f2tf32(A[(mr + 8) * GAP + kk * 8 + c]);
                af[mt][2] = f2tf32(A[mr * GAP + kk * 8 + c + 4]);
                af[mt][3] = f2tf32(A[(mr + 8) * GAP + kk * 8 + c + 4]);
            }
#pragma unroll
            for (int nt = 0; nt < 4; ++nt) {
                int nc = warp_n * 32 + nt * 8 + g;
                uint32_t b0 = f2tf32(B[(kk * 8 + c) * GBP + nc]);
                uint32_t b1 = f2tf32(B[(kk * 8 + c + 4) * GBP + nc]);
#pragma unroll
                for (int mt = 0; mt < 2; ++mt)
                    mma_tf32(acc[mt][nt][0], acc[mt][nt][1], acc[mt][nt][2], acc[mt][nt][3],
                             af[mt][0], af[mt][1], af[mt][2], af[mt][3], b0, b1);
            }
        }
        __syncthreads();
    }

    const int sel = n0 / D_MODEL;
    const int head = (n0 % D_MODEL) / WHEAD;

#pragma unroll
    for (int mt = 0; mt < 2; ++mt) {
#pragma unroll
        for (int nt = 0; nt < 4; ++nt) {
            int w = warp_n * 32 + nt * 8 + 2 * c;
            float b0 = bq[n0 + w], b1 = bq[n0 + w + 1];
            int m_lo = m0 + warp_m * 32 + mt * 16 + g;
            float v00 = acc[mt][nt][0] + b0;
            float v01 = acc[mt][nt][1] + b1;
            float v10 = acc[mt][nt][2] + b0;
            float v11 = acc[mt][nt][3] + b1;
            if (sel == 2) {   // V transposed: [h][w][s]
                __half* vt = g_vt + (size_t)head * WHEAD * S_LEN;
                vt[(size_t)w * S_LEN + m_lo] = __float2half_rn(v00);
                vt[(size_t)(w + 1) * S_LEN + m_lo] = __float2half_rn(v01);
                vt[(size_t)w * S_LEN + m_lo + 8] = __float2half_rn(v10);
                vt[(size_t)(w + 1) * S_LEN + m_lo + 8] = __float2half_rn(v11);
            } else {          // Q/K natural: [h][s][w]
                __half* dst = (sel == 0) ? g_q : g_k;
                *(__half2*)&dst[((size_t)head * S_LEN + m_lo) * WHEAD + w] =
                    __floats2half2_rn(v00, v01);
                *(__half2*)&dst[((size_t)head * S_LEN + m_lo + 8) * WHEAD + w] =
                    __floats2half2_rn(v10, v11);
            }
        }
    }
}

// =============== Kernel 2: flash attention (fp16 MMA, BC=32, split-KV x4) ===============
#define QP  72    // 144 B row stride; word-stride 36 == 4 (mod 32)
#define KPH 72
#define VPH 40    // 80 B row stride; word-stride 20 -> all phases distinct
#define SM_Q   0
#define SM_K   (128 * QP)              // 9216
#define SM_V   (SM_K + 32 * KPH)       // 11520
#define SM_END (SM_V + 64 * VPH)       // 14080 halves
#define SM_AM_F (SM_END / 2)           // float index of mask area
#define ATTN_SMEM_BYTES (SM_END * 2 + 2 * 32 * 4)   // 28416 B

#define LOG2E 1.4426950408889634f
#define SCL   (0.125f * LOG2E)
#define AMC   (10000.0f * LOG2E)

__global__ __launch_bounds__(128, 4) void attn_tc(
    const float* __restrict__ mask)
{
    extern __shared__ __half smh[];
    float* smf = (float*)smh;

    const int tid = threadIdx.x;
    const int wid = tid >> 5;
    const int lane = tid & 31;
    const int g = lane >> 2;
    const int c = lane & 3;
    const int r0 = blockIdx.x * 128;
    const int head = blockIdx.y;
    const int split = blockIdx.z;
    const int tb = split * NT_PER;

    const __half* qh = g_q + (size_t)head * S_LEN * WHEAD;
    const __half* kh = g_k + (size_t)head * S_LEN * WHEAD;
    const __half* vt = g_vt + (size_t)head * WHEAD * S_LEN;

    const int r8 = tid >> 3, c8 = tid & 7;
    const int r4 = tid >> 2, c4 = tid & 3;

    auto issueK = [&](int t0) {
#pragma unroll
        for (int r = 0; r < 2; ++r) {
            int row = r8 + r * 16;
            cpa16(&smh[SM_K + row * KPH + c8 * 8],
                  &kh[(size_t)(t0 + row) * WHEAD + c8 * 8]);
        }
        if (tid < 8) cpa16(&smf[SM_AM_F + ((t0 >> 5) & 1) * 32 + tid * 4], &mask[t0 + tid * 4]);
    };
    auto issueV = [&](int t0) {
#pragma unroll
        for (int r = 0; r < 2; ++r) {
            int w = r4 + r * 32;
            cpa16(&smh[SM_V + w * VPH + c4 * 8],
                  &vt[(size_t)w * S_LEN + t0 + c4 * 8]);
        }
    };

    // ---- prologue ----
#pragma unroll
    for (int r = 0; r < 8; ++r) {
        int row = r8 + r * 16;
        cpa16(&smh[SM_Q + row * QP + c8 * 8],
              &qh[(size_t)(r0 + row) * WHEAD + c8 * 8]);
    }
    issueK(tb * 32);
    issueV(tb * 32);
    CPA_COMMIT();

    float oacc[2][8][4];
#pragma unroll
    for (int mt = 0; mt < 2; ++mt)
#pragma unroll
        for (int nt = 0; nt < 8; ++nt)
#pragma unroll
            for (int i = 0; i < 4; ++i) oacc[mt][nt][i] = 0.0f;
    float lrow[2][2];
    lrow[0][0] = lrow[0][1] = lrow[1][0] = lrow[1][1] = 0.0f;

    CPA_WAIT0();
    __syncthreads();

    for (int tt = 0; tt < NT_PER; ++tt) {
        const int t = tb + tt;

        // ---- S = Q K^T : fp16 m16n8k16, 4 k-steps ----
        float sacc[2][4][4];
#pragma unroll
        for (int mt = 0; mt < 2; ++mt)
#pragma unroll
            for (int nt = 0; nt < 4; ++nt)
#pragma unroll
                for (int i = 0; i < 4; ++i) sacc[mt][nt][i] = 0.0f;

#pragma unroll
        for (int kk = 0; kk < 4; ++kk) {
            uint32_t af[2][4];
#pragma unroll
            for (int mt = 0; mt < 2; ++mt) {
                int mr = wid * 32 + mt * 16 + g;
                af[mt][0] = *(const uint32_t*)&smh[SM_Q + mr * QP + kk * 16 + 2 * c];
                af[mt][1] = *(const uint32_t*)&smh[SM_Q + (mr + 8) * QP + kk * 16 + 2 * c];
                af[mt][2] = *(const uint32_t*)&smh[SM_Q + mr * QP + kk * 16 + 8 + 2 * c];
                af[mt][3] = *(const uint32_t*)&smh[SM_Q + (mr + 8) * QP + kk * 16 + 8 + 2 * c];
            }
#pragma unroll
            for (int nt = 0; nt < 4; ++nt) {
                int kr = nt * 8 + g;
                uint32_t b0 = *(const uint32_t*)&smh[SM_K + kr * KPH + kk * 16 + 2 * c];
                uint32_t b1 = *(const uint32_t*)&smh[SM_K + kr * KPH + kk * 16 + 8 + 2 * c];
#pragma unroll
                for (int mt = 0; mt < 2; ++mt)
                    mma_f16(sacc[mt][nt][0], sacc[mt][nt][1], sacc[mt][nt][2], sacc[mt][nt][3],
                            af[mt][0], af[mt][1], af[mt][2], af[mt][3], b0, b1);
            }
        }

        __syncthreads();                   // K readers done
        if (tt + 1 < NT_PER) issueK((t + 1) * 32);
        CPA_COMMIT();                      // group = K(t+1)+mask(t+1)

        // ---- static-max softmax ----
        {
            float amv[4][2];
#pragma unroll
            for (int nt = 0; nt < 4; ++nt) {
                float m0v = smf[SM_AM_F + (t & 1) * 32 + nt * 8 + 2 * c];
                float m1v = smf[SM_AM_F + (t & 1) * 32 + nt * 8 + 2 * c + 1];
                amv[nt][0] = fmaf(m0v, AMC, -AMC);
                amv[nt][1] = fmaf(m1v, AMC, -AMC);
            }
#pragma unroll
            for (int mt = 0; mt < 2; ++mt) {
#pragma unroll
                for (int nt = 0; nt < 4; ++nt) {
                    float p0 = ex2(fmaf(sacc[mt][nt][0], SCL, amv[nt][0]));
                    float p1 = ex2(fmaf(sacc[mt][nt][1], SCL, amv[nt][1]));
                    float p2 = ex2(fmaf(sacc[mt][nt][2], SCL, amv[nt][0]));
                    float p3 = ex2(fmaf(sacc[mt][nt][3], SCL, amv[nt][1]));
                    lrow[mt][0] += p0 + p1;
                    lrow[mt][1] += p2 + p3;
                    sacc[mt][nt][0] = p0;
                    sacc[mt][nt][1] = p1;
                    sacc[mt][nt][2] = p2;
                    sacc[mt][nt][3] = p3;
                }
            }
        }

        CPA_WAIT1();                       // V(t)'s group (older) retired
        __syncthreads();

        // ---- O += P V : fp16 m16n8k16, 2 k-steps; A-frags = packed C-frags ----
#pragma unroll
        for (int q = 0; q < 2; ++q) {
            uint32_t af[2][4];
#pragma unroll
            for (int mt = 0; mt < 2; ++mt) {
                af[mt][0] = pack2(sacc[mt][2 * q][0], sacc[mt][2 * q][1]);
                af[mt][1] = pack2(sacc[mt][2 * q][2], sacc[mt][2 * q][3]);
                af[mt][2] = pack2(sacc[mt][2 * q + 1][0], sacc[mt][2 * q + 1][1]);
                af[mt][3] = pack2(sacc[mt][2 * q + 1][2], sacc[mt][2 * q + 1][3]);
            }
#pragma unroll
            for (int nt = 0; nt < 8; ++nt) {
                int vr = nt * 8 + g;
                uint32_t b0 = *(const uint32_t*)&smh[SM_V + vr * VPH + q * 16 + 2 * c];
                uint32_t b1 = *(const uint32_t*)&smh[SM_V + vr * VPH + q * 16 + 8 + 2 * c];
#pragma unroll
                for (int mt = 0; mt < 2; ++mt)
                    mma_f16(oacc[mt][nt][0], oacc[mt][nt][1], oacc[mt][nt][2], oacc[mt][nt][3],
                            af[mt][0], af[mt][1], af[mt][2], af[mt][3], b0, b1);
            }
        }

        __syncthreads();                   // V readers done
        if (tt + 1 < NT_PER) issueV((t + 1) * 32);
        CPA_COMMIT();                      // group = V(t+1)
        CPA_WAIT1();                       // K(t+1) retired
        __syncthreads();
    }

    // ---- epilogue: quad-reduce l, write unnormalized partials ----
    float* op = g_os + ((size_t)(split * NHEAD + head) * S_LEN) * WHEAD;
    float* lp = g_ls + (size_t)(split * NHEAD + head) * S_LEN;
#pragma unroll
    for (int mt = 0; mt < 2; ++mt) {
#pragma unroll
        for (int off = 1; off <= 2; off <<= 1) {
            lrow[mt][0] += __shfl_xor_sync(0xffffffffu, lrow[mt][0], off);
            lrow[mt][1] += __shfl_xor_sync(0xffffffffu, lrow[mt][1], off);
        }
        int row_lo = r0 + wid * 32 + mt * 16 + g;
        if (c == 0) {
            lp[row_lo] = lrow[mt][0];
            lp[row_lo + 8] = lrow[mt][1];
        }
#pragma unroll
        for (int nt = 0; nt < 8; ++nt) {
            int col = nt * 8 + 2 * c;
            *(float2*)&op[(size_t)row_lo * WHEAD + col] =
                make_float2(oacc[mt][nt][0], oacc[mt][nt][1]);
            *(float2*)&op[(size_t)(row_lo + 8) * WHEAD + col] =
                make_float2(oacc[mt][nt][2], oacc[mt][nt][3]);
        }
    }
}

// =============== Kernel 3: combine splits ===============
__global__ __launch_bounds__(256) void combine_k(float* __restrict__ out)
{
    int idx = blockIdx.x * 256 + threadIdx.x;
    int w4 = idx & 15;
    int hs = idx >> 4;
    int h = hs % NHEAD;
    int s = hs / NHEAD;

    float4 o = make_float4(0.f, 0.f, 0.f, 0.f);
    float l = 0.f;
#pragma unroll
    for (int p = 0; p < NSPLIT; ++p) {
        const float* op = g_os + (((size_t)(p * NHEAD + h) * S_LEN + s) * WHEAD);
        float4 v = *(const float4*)&op[w4 * 4];
        o.x += v.x; o.y += v.y; o.z += v.z; o.w += v.w;
        l += g_ls[(size_t)(p * NHEAD + h) * S_LEN + s];
    }
    float inv = 1.0f / l;
    o.x *= inv; o.y *= inv; o.z *= inv; o.w *= inv;
    *(float4*)&out[(size_t)s * D_MODEL + h * WHEAD + w4 * 4] = o;
}

// ---------------- launch ----------------
extern "C" void kernel_launch(void* const* d_in, const int* in_sizes, int n_in,
                              void* d_out, int out_size)
{
    const float* x    = (const float*)d_in[0];
    const float* mask = (const float*)d_in[1];
    const float* Wq   = (const float*)d_in[2];
    const float* bq   = (const float*)d_in[3];
    float* out = (float*)d_out;

    dim3 gGemm(N_QKV / 64, S_LEN / 128);         // (36, 32)
    qkv_gemm_tc<<<gGemm, 256>>>(x, Wq, bq);

    cudaFuncSetAttribute(attn_tc,
                         cudaFuncAttributeMaxDynamicSharedMemorySize,
                         ATTN_SMEM_BYTES);
    dim3 gAttn(S_LEN / 128, NHEAD, NSPLIT);      // (32, 12, 4)
    attn_tc<<<gAttn, 128, ATTN_SMEM_BYTES>>>(mask);

    combine_k<<<(S_LEN * NHEAD * 16) / 256, 256>>>(out);
}

// round 17
// speedup vs baseline: 1.5665x; 1.0573x over previous
#include <cuda_runtime.h>
#include <cuda_fp16.h>
#include <cstdint>

#define S_LEN 4096
#define D_MODEL 768
#define NHEAD 12
#define WHEAD 64
#define N_QKV 2304
#define NSPLIT 4
#define NT_KV (S_LEN / 32)
#define NT_PER (NT_KV / NSPLIT)

// ---------------- scratch ----------------
__device__ __half g_q[NHEAD * S_LEN * WHEAD];   // [h][s][w] fp16
__device__ __half g_k[NHEAD * S_LEN * WHEAD];   // [h][s][w] fp16
__device__ __half g_vt[NHEAD * WHEAD * S_LEN];  // [h][w][s] fp16 (transposed)
__device__ float g_os[NSPLIT * NHEAD * S_LEN * WHEAD];
__device__ float g_ls[NSPLIT * NHEAD * S_LEN];

// ---------------- helpers ----------------
__device__ __forceinline__ float ex2(float x) {
    float y;
    asm("ex2.approx.f32 %0, %1;" : "=f"(y) : "f"(x));
    return y;
}
// pack (lo,hi) floats -> f16x2 (lo in bits[15:0])
__device__ __forceinline__ uint32_t pack2(float lo, float hi) {
    uint32_t r;
    asm("cvt.rn.f16x2.f32 %0, %1, %2;" : "=r"(r) : "f"(hi), "f"(lo));
    return r;
}

__device__ __forceinline__ void mma_f16(
    float& d0, float& d1, float& d2, float& d3,
    uint32_t a0, uint32_t a1, uint32_t a2, uint32_t a3,
    uint32_t b0, uint32_t b1)
{
    asm volatile(
        "mma.sync.aligned.m16n8k16.row.col.f32.f16.f16.f32 "
        "{%0,%1,%2,%3},{%4,%5,%6,%7},{%8,%9},{%0,%1,%2,%3};"
        : "+f"(d0), "+f"(d1), "+f"(d2), "+f"(d3)
        : "r"(a0), "r"(a1), "r"(a2), "r"(a3), "r"(b0), "r"(b1));
}

__device__ __forceinline__ void cpa16(void* s, const void* g) {
    uint32_t sa = (uint32_t)__cvta_generic_to_shared(s);
    asm volatile("cp.async.cg.shared.global [%0], [%1], 16;" :: "r"(sa), "l"(g));
}
#define CPA_COMMIT() asm volatile("cp.async.commit_group;" ::: "memory")
#define CPA_WAIT0()  asm volatile("cp.async.wait_group 0;" ::: "memory")
#define CPA_WAIT1()  asm volatile("cp.async.wait_group 1;" ::: "memory")

// =============== Kernel 1: QKV GEMM (fp32 staging, fused fp16 MMA) ===============
// 128x64 tile, BK=32, 256 threads = 8 warps (4m x 2n).
// A pitch 40 floats (row-stride 8 mod 32: LDS.64 k-pair loads conflict-free);
// B pitch 68 floats (2*68 mod 32 = 8: scalar k-pair loads conflict-free).
#define GAP 40
#define GBP 68
#define GA_SZ (128 * GAP)        // 5120 floats
#define GB_SZ (32 * GBP)         // 2176 floats
#define GEMM_SMEM_BYTES ((GA_SZ + GB_SZ) * 2 * 4)   // 58368 B -> exactly 4 CTAs/SM

__global__ __launch_bounds__(256) void qkv_gemm_tc(
    const float* __restrict__ X, const float* __restrict__ Wq,
    const float* __restrict__ bq)
{
    extern __shared__ float gsm[];
    float* As[2] = { gsm, gsm + GA_SZ + GB_SZ };
    float* Bs[2] = { gsm + GA_SZ, gsm + GA_SZ + GB_SZ + GA_SZ };

    const int tid = threadIdx.x;
    const int wid = tid >> 5;
    const int lane = tid & 31;
    const int g = lane >> 2;
    const int c = lane & 3;
    const int warp_m = wid >> 1;
    const int warp_n = wid & 1;
    const int m0 = blockIdx.y * 128;
    const int n0 = blockIdx.x * 64;

    float acc[2][4][4];
#pragma unroll
    for (int mt = 0; mt < 2; ++mt)
#pragma unroll
        for (int nt = 0; nt < 4; ++nt)
#pragma unroll
            for (int i = 0; i < 4; ++i) acc[mt][nt][i] = 0.0f;

    const int rowA = tid >> 3, c4A = tid & 7;
    const int rowB = tid >> 4, c4B = tid & 15;

    auto issue = [&](int k0, int buf) {
#pragma unroll
        for (int r = 0; r < 4; ++r) {
            int row = rowA + r * 32;
            cpa16(&As[buf][row * GAP + c4A * 4],
                  &X[(size_t)(m0 + row) * D_MODEL + k0 + c4A * 4]);
        }
#pragma unroll
        for (int r = 0; r < 2; ++r) {
            int row = rowB + r * 16;
            cpa16(&Bs[buf][row * GBP + c4B * 4],
                  &Wq[(size_t)(k0 + row) * N_QKV + n0 + c4B * 4]);
        }
        CPA_COMMIT();
    };

    issue(0, 0);
    for (int i = 0; i < 24; ++i) {
        CPA_WAIT0();
        __syncthreads();
        if (i + 1 < 24) issue((i + 1) * 32, (i + 1) & 1);
        const float* A = As[i & 1];
        const float* B = Bs[i & 1];
#pragma unroll
        for (int ks = 0; ks < 2; ++ks) {           // two k16 steps per BK=32
            uint32_t af[2][4];
#pragma unroll
            for (int mt = 0; mt < 2; ++mt) {
                int mr = warp_m * 32 + mt * 16 + g;
                float2 a0 = *(const float2*)&A[mr * GAP + ks * 16 + 2 * c];
                float2 a1 = *(const float2*)&A[(mr + 8) * GAP + ks * 16 + 2 * c];
                float2 a2 = *(const float2*)&A[mr * GAP + ks * 16 + 8 + 2 * c];
                float2 a3 = *(const float2*)&A[(mr + 8) * GAP + ks * 16 + 8 + 2 * c];
                af[mt][0] = pack2(a0.x, a0.y);
                af[mt][1] = pack2(a1.x, a1.y);
                af[mt][2] = pack2(a2.x, a2.y);
                af[mt][3] = pack2(a3.x, a3.y);
            }
#pragma unroll
            for (int nt = 0; nt < 4; ++nt) {
                int col = warp_n * 32 + nt * 8 + g;
                int kr = ks * 16 + 2 * c;
                uint32_t b0 = pack2(B[kr * GBP + col], B[(kr + 1) * GBP + col]);
                uint32_t b1 = pack2(B[(kr + 8) * GBP + col], B[(kr + 9) * GBP + col]);
#pragma unroll
                for (int mt = 0; mt < 2; ++mt)
                    mma_f16(acc[mt][nt][0], acc[mt][nt][1], acc[mt][nt][2], acc[mt][nt][3],
                            af[mt][0], af[mt][1], af[mt][2], af[mt][3], b0, b1);
            }
        }
        __syncthreads();
    }

    const int sel = n0 / D_MODEL;
    const int head = (n0 % D_MODEL) / WHEAD;

#pragma unroll
    for (int mt = 0; mt < 2; ++mt) {
#pragma unroll
        for (int nt = 0; nt < 4; ++nt) {
            int w = warp_n * 32 + nt * 8 + 2 * c;
            float b0 = bq[n0 + w], b1 = bq[n0 + w + 1];
            int m_lo = m0 + warp_m * 32 + mt * 16 + g;
            float v00 = acc[mt][nt][0] + b0;
            float v01 = acc[mt][nt][1] + b1;
            float v10 = acc[mt][nt][2] + b0;
            float v11 = acc[mt][nt][3] + b1;
            if (sel == 2) {   // V transposed: [h][w][s]
                __half* vt = g_vt + (size_t)head * WHEAD * S_LEN;
                vt[(size_t)w * S_LEN + m_lo] = __float2half_rn(v00);
                vt[(size_t)(w + 1) * S_LEN + m_lo] = __float2half_rn(v01);
                vt[(size_t)w * S_LEN + m_lo + 8] = __float2half_rn(v10);
                vt[(size_t)(w + 1) * S_LEN + m_lo + 8] = __float2half_rn(v11);
            } else {          // Q/K natural: [h][s][w]
                __half* dst = (sel == 0) ? g_q : g_k;
                *(__half2*)&dst[((size_t)head * S_LEN + m_lo) * WHEAD + w] =
                    __floats2half2_rn(v00, v01);
                *(__half2*)&dst[((size_t)head * S_LEN + m_lo + 8) * WHEAD + w] =
                    __floats2half2_rn(v10, v11);
            }
        }
    }
}

// =============== Kernel 2: flash attention (fp16 MMA, BC=32, split-KV x4) ===============
#define QP  72
#define KPH 72
#define VPH 40
#define SM_Q   0
#define SM_K   (128 * QP)
#define SM_V   (SM_K + 32 * KPH)
#define SM_END (SM_V + 64 * VPH)
#define SM_AM_F (SM_END / 2)
#define ATTN_SMEM_BYTES (SM_END * 2 + 2 * 32 * 4)   // 28416 B

#define LOG2E 1.4426950408889634f
#define SCL   (0.125f * LOG2E)
#define AMC   (10000.0f * LOG2E)

__global__ __launch_bounds__(128, 4) void attn_tc(
    const float* __restrict__ mask)
{
    extern __shared__ __half smh[];
    float* smf = (float*)smh;

    const int tid = threadIdx.x;
    const int wid = tid >> 5;
    const int lane = tid & 31;
    const int g = lane >> 2;
    const int c = lane & 3;
    const int r0 = blockIdx.x * 128;
    const int head = blockIdx.y;
    const int split = blockIdx.z;
    const int tb = split * NT_PER;

    const __half* qh = g_q + (size_t)head * S_LEN * WHEAD;
    const __half* kh = g_k + (size_t)head * S_LEN * WHEAD;
    const __half* vt = g_vt + (size_t)head * WHEAD * S_LEN;

    const int r8 = tid >> 3, c8 = tid & 7;
    const int r4 = tid >> 2, c4 = tid & 3;

    auto issueK = [&](int t0) {
#pragma unroll
        for (int r = 0; r < 2; ++r) {
            int row = r8 + r * 16;
            cpa16(&smh[SM_K + row * KPH + c8 * 8],
                  &kh[(size_t)(t0 + row) * WHEAD + c8 * 8]);
        }
        if (tid < 8) cpa16(&smf[SM_AM_F + ((t0 >> 5) & 1) * 32 + tid * 4], &mask[t0 + tid * 4]);
    };
    auto issueV = [&](int t0) {
#pragma unroll
        for (int r = 0; r < 2; ++r) {
            int w = r4 + r * 32;
            cpa16(&smh[SM_V + w * VPH + c4 * 8],
                  &vt[(size_t)w * S_LEN + t0 + c4 * 8]);
        }
    };

    // ---- prologue ----
#pragma unroll
    for (int r = 0; r < 8; ++r) {
        int row = r8 + r * 16;
        cpa16(&smh[SM_Q + row * QP + c8 * 8],
              &qh[(size_t)(r0 + row) * WHEAD + c8 * 8]);
    }
    issueK(tb * 32);
    issueV(tb * 32);
    CPA_COMMIT();

    float oacc[2][8][4];
#pragma unroll
    for (int mt = 0; mt < 2; ++mt)
#pragma unroll
        for (int nt = 0; nt < 8; ++nt)
#pragma unroll
            for (int i = 0; i < 4; ++i) oacc[mt][nt][i] = 0.0f;
    float lrow[2][2];
    lrow[0][0] = lrow[0][1] = lrow[1][0] = lrow[1][1] = 0.0f;

    CPA_WAIT0();
    __syncthreads();

    for (int tt = 0; tt < NT_PER; ++tt) {
        const int t = tb + tt;

        // ---- S = Q K^T : fp16 m16n8k16, 4 k-steps ----
        float sacc[2][4][4];
#pragma unroll
        for (int mt = 0; mt < 2; ++mt)
#pragma unroll
            for (int nt = 0; nt < 4; ++nt)
#pragma unroll
                for (int i = 0; i < 4; ++i) sacc[mt][nt][i] = 0.0f;

#pragma unroll
        for (int kk = 0; kk < 4; ++kk) {
            uint32_t af[2][4];
#pragma unroll
            for (int mt = 0; mt < 2; ++mt) {
                int mr = wid * 32 + mt * 16 + g;
                af[mt][0] = *(const uint32_t*)&smh[SM_Q + mr * QP + kk * 16 + 2 * c];
                af[mt][1] = *(const uint32_t*)&smh[SM_Q + (mr + 8) * QP + kk * 16 + 2 * c];
                af[mt][2] = *(const uint32_t*)&smh[SM_Q + mr * QP + kk * 16 + 8 + 2 * c];
                af[mt][3] = *(const uint32_t*)&smh[SM_Q + (mr + 8) * QP + kk * 16 + 8 + 2 * c];
            }
#pragma unroll
            for (int nt = 0; nt < 4; ++nt) {
                int kr = nt * 8 + g;
                uint32_t b0 = *(const uint32_t*)&smh[SM_K + kr * KPH + kk * 16 + 2 * c];
                uint32_t b1 = *(const uint32_t*)&smh[SM_K + kr * KPH + kk * 16 + 8 + 2 * c];
#pragma unroll
                for (int mt = 0; mt < 2; ++mt)
                    mma_f16(sacc[mt][nt][0], sacc[mt][nt][1], sacc[mt][nt][2], sacc[mt][nt][3],
                            af[mt][0], af[mt][1], af[mt][2], af[mt][3], b0, b1);
            }
        }

        __syncthreads();                   // K readers done
        if (tt + 1 < NT_PER) issueK((t + 1) * 32);
        CPA_COMMIT();                      // group = K(t+1)+mask(t+1)

        // ---- static-max softmax ----
        {
            float amv[4][2];
#pragma unroll
            for (int nt = 0; nt < 4; ++nt) {
                float m0v = smf[SM_AM_F + (t & 1) * 32 + nt * 8 + 2 * c];
                float m1v = smf[SM_AM_F + (t & 1) * 32 + nt * 8 + 2 * c + 1];
                amv[nt][0] = fmaf(m0v, AMC, -AMC);
                amv[nt][1] = fmaf(m1v, AMC, -AMC);
            }
#pragma unroll
            for (int mt = 0; mt < 2; ++mt) {
#pragma unroll
                for (int nt = 0; nt < 4; ++nt) {
                    float p0 = ex2(fmaf(sacc[mt][nt][0], SCL, amv[nt][0]));
                    float p1 = ex2(fmaf(sacc[mt][nt][1], SCL, amv[nt][1]));
                    float p2 = ex2(fmaf(sacc[mt][nt][2], SCL, amv[nt][0]));
                    float p3 = ex2(fmaf(sacc[mt][nt][3], SCL, amv[nt][1]));
                    lrow[mt][0] += p0 + p1;
                    lrow[mt][1] += p2 + p3;
                    sacc[mt][nt][0] = p0;
                    sacc[mt][nt][1] = p1;
                    sacc[mt][nt][2] = p2;
                    sacc[mt][nt][3] = p3;
                }
            }
        }

        CPA_WAIT1();                       // V(t)'s group (older) retired
        __syncthreads();

        // ---- O += P V : fp16 m16n8k16, 2 k-steps; A-frags = packed C-frags ----
#pragma unroll
        for (int q = 0; q < 2; ++q) {
            uint32_t af[2][4];
#pragma unroll
            for (int mt = 0; mt < 2; ++mt) {
                af[mt][0] = pack2(sacc[mt][2 * q][0], sacc[mt][2 * q][1]);
                af[mt][1] = pack2(sacc[mt][2 * q][2], sacc[mt][2 * q][3]);
                af[mt][2] = pack2(sacc[mt][2 * q + 1][0], sacc[mt][2 * q + 1][1]);
                af[mt][3] = pack2(sacc[mt][2 * q + 1][2], sacc[mt][2 * q + 1][3]);
            }
#pragma unroll
            for (int nt = 0; nt < 8; ++nt) {
                int vr = nt * 8 + g;
                uint32_t b0 = *(const uint32_t*)&smh[SM_V + vr * VPH + q * 16 + 2 * c];
                uint32_t b1 = *(const uint32_t*)&smh[SM_V + vr * VPH + q * 16 + 8 + 2 * c];
#pragma unroll
                for (int mt = 0; mt < 2; ++mt)
                    mma_f16(oacc[mt][nt][0], oacc[mt][nt][1], oacc[mt][nt][2], oacc[mt][nt][3],
                            af[mt][0], af[mt][1], af[mt][2], af[mt][3], b0, b1);
            }
        }

        __syncthreads();                   // V readers done
        if (tt + 1 < NT_PER) issueV((t + 1) * 32);
        CPA_COMMIT();                      // group = V(t+1)
        CPA_WAIT1();                       // K(t+1) retired
        __syncthreads();
    }

    // ---- epilogue: quad-reduce l, write unnormalized partials ----
    float* op = g_os + ((size_t)(split * NHEAD + head) * S_LEN) * WHEAD;
    float* lp = g_ls + (size_t)(split * NHEAD + head) * S_LEN;
#pragma unroll
    for (int mt = 0; mt < 2; ++mt) {
#pragma unroll
        for (int off = 1; off <= 2; off <<= 1) {
            lrow[mt][0] += __shfl_xor_sync(0xffffffffu, lrow[mt][0], off);
            lrow[mt][1] += __shfl_xor_sync(0xffffffffu, lrow[mt][1], off);
        }
        int row_lo = r0 + wid * 32 + mt * 16 + g;
        if (c == 0) {
            lp[row_lo] = lrow[mt][0];
            lp[row_lo + 8] = lrow[mt][1];
        }
#pragma unroll
        for (int nt = 0; nt < 8; ++nt) {
            int col = nt * 8 + 2 * c;
            *(float2*)&op[(size_t)row_lo * WHEAD + col] =
                make_float2(oacc[mt][nt][0], oacc[mt][nt][1]);
            *(float2*)&op[(size_t)(row_lo + 8) * WHEAD + col] =
                make_float2(oacc[mt][nt][2], oacc[mt][nt][3]);
        }
    }
}

// =============== Kernel 3: combine splits ===============
__global__ __launch_bounds__(256) void combine_k(float* __restrict__ out)
{
    int idx = blockIdx.x * 256 + threadIdx.x;
    int w4 = idx & 15;
    int hs = idx >> 4;
    int h = hs % NHEAD;
    int s = hs / NHEAD;

    float4 o = make_float4(0.f, 0.f, 0.f, 0.f);
    float l = 0.f;
#pragma unroll
    for (int p = 0; p < NSPLIT; ++p) {
        const float* op = g_os + (((size_t)(p * NHEAD + h) * S_LEN + s) * WHEAD);
        float4 v = *(const float4*)&op[w4 * 4];
        o.x += v.x; o.y += v.y; o.z += v.z; o.w += v.w;
        l += g_ls[(size_t)(p * NHEAD + h) * S_LEN + s];
    }
    float inv = 1.0f / l;
    o.x *= inv; o.y *= inv; o.z *= inv; o.w *= inv;
    *(float4*)&out[(size_t)s * D_MODEL + h * WHEAD + w4 * 4] = o;
}

// ---------------- launch ----------------
extern "C" void kernel_launch(void* const* d_in, const int* in_sizes, int n_in,
                              void* d_out, int out_size)
{
    const float* x    = (const float*)d_in[0];
    const float* mask = (const float*)d_in[1];
    const float* Wq   = (const float*)d_in[2];
    const float* bq   = (const float*)d_in[3];
    float* out = (float*)d_out;

    cudaFuncSetAttribute(qkv_gemm_tc,
                         cudaFuncAttributeMaxDynamicSharedMemorySize,
                         GEMM_SMEM_BYTES);
    dim3 gGemm(N_QKV / 64, S_LEN / 128);         // (36, 32)
    qkv_gemm_tc<<<gGemm, 256, GEMM_SMEM_BYTES>>>(x, Wq, bq);

    cudaFuncSetAttribute(attn_tc,
                         cudaFuncAttributeMaxDynamicSharedMemorySize,
                         ATTN_SMEM_BYTES);
    dim3 gAttn(S_LEN / 128, NHEAD, NSPLIT);      // (32, 12, 4)
    attn_tc<<<gAttn, 128, ATTN_SMEM_BYTES>>>(mask);

    combine_k<<<(S_LEN * NHEAD * 16) / 256, 256>>>(out);
}